// round 3
// baseline (speedup 1.0000x reference)
#include <cuda_runtime.h>
#include <cuda_bf16.h>
#include <cstdint>

#define N_NODES 50000
#define N_EDGES 800000
#define IN_DIM  128
#define HID     128
#define OUT_DIM 64

typedef unsigned long long u64;

// Scratch (device globals — no allocations allowed)
__device__ int   g_idx64;                           // 1 if edge_index is int64
__device__ int   g_deg[N_NODES];
__device__ float g_dinv[N_NODES];
__device__ float g_agg[(size_t)N_NODES * IN_DIM];   // aggregated raw h (25.6 MB)
__device__ float g_Wgt[HID * IN_DIM];               // W_gcn transposed: [c][k]
__device__ float g_Wft[OUT_DIM * HID];              // W_fc  transposed: [c][k]

// ---- f32x2 packed helpers (FFMA2 path: scalar FFMA is half-rate on sm_103a) ----
__device__ __forceinline__ u64 fma2(u64 a, u64 b, u64 c) {
    u64 d;
    asm("fma.rn.f32x2 %0, %1, %2, %3;" : "=l"(d) : "l"(a), "l"(b), "l"(c));
    return d;
}
__device__ __forceinline__ u64 packf2(float lo, float hi) {
    u64 r;
    asm("mov.b64 %0, {%1, %2};" : "=l"(r) : "f"(lo), "f"(hi));
    return r;
}
__device__ __forceinline__ float hadd2(u64 v) {
    float lo, hi;
    asm("mov.b64 {%0, %1}, %2;" : "=f"(lo), "=f"(hi) : "l"(v));
    return lo + hi;
}

__device__ __forceinline__ int edge_idx(const void* ei, int i) {
    if (g_idx64) return (int)((const long long*)ei)[i];
    return ((const int*)ei)[i];
}

// ---------------------------------------------------------------------------
// k0: fused init — degree=1 (self-loop), transpose weights, dtype detect
// ---------------------------------------------------------------------------
__global__ void k_init(const void* __restrict__ ei,
                       const float* __restrict__ Wg,
                       const float* __restrict__ Wf) {
    int i = blockIdx.x * blockDim.x + threadIdx.x;
    if (i < N_NODES) g_deg[i] = 1;
    if (i < IN_DIM * HID) {                 // Wg[k][c] -> Wgt[c][k]
        int k = i >> 7, c = i & 127;
        g_Wgt[c * IN_DIM + k] = Wg[i];
    }
    if (i < HID * OUT_DIM) {                // Wf[k][c] -> Wft[c][k]
        int k = i / OUT_DIM, c = i % OUT_DIM;
        g_Wft[c * HID + k] = Wf[i];
    }
    // dtype detection: int64 interpretation of first 256 entries all in-range
    // => truly int64 (prob. of false positive on int32 data ~ 0).
    if (blockIdx.x == 0) {
        __shared__ int s_ok;
        if (threadIdx.x == 0) s_ok = 1;
        __syncthreads();
        long long v = ((const long long*)ei)[threadIdx.x];  // 2KB, in-bounds either way
        if (v < 0 || v >= N_NODES) atomicAnd(&s_ok, 0);
        __syncthreads();
        if (threadIdx.x == 0) g_idx64 = s_ok;
    }
}

// ---------------------------------------------------------------------------
// k1: in-degree histogram over destination column
// ---------------------------------------------------------------------------
__global__ void k_deg_count(const void* __restrict__ ei) {
    int e = blockIdx.x * blockDim.x + threadIdx.x;
    if (e < N_EDGES) {
        int c = edge_idx(ei, N_EDGES + e);
        atomicAdd(&g_deg[c], 1);
    }
}

// ---------------------------------------------------------------------------
// k2: fused dinv + self-loop init:  agg[i] = h[i]/deg[i],  dinv[i]=rsqrt(deg)
// ---------------------------------------------------------------------------
__global__ void k_dinv_self(const float* __restrict__ h) {
    int idx = blockIdx.x * blockDim.x + threadIdx.x;
    if (idx >= N_NODES * 32) return;
    int node = idx >> 5;
    float deg = (float)g_deg[node];
    if ((idx & 31) == 0) g_dinv[node] = rsqrtf(deg);
    float s = 1.0f / deg;                    // == dinv^2
    float4 v = ((const float4*)h)[idx];
    v.x *= s; v.y *= s; v.z *= s; v.w *= s;
    ((float4*)g_agg)[idx] = v;
}

// ---------------------------------------------------------------------------
// k3: edge scatter: agg[col] += h[row] * (dinv[row]*dinv[col])
//     one warp per edge; lane = one float4; red.global.add.v4.f32
// ---------------------------------------------------------------------------
__global__ void __launch_bounds__(256) k_scatter(const float* __restrict__ h,
                                                 const void* __restrict__ ei) {
    int warp = (blockIdx.x * blockDim.x + threadIdx.x) >> 5;
    if (warp >= N_EDGES) return;
    int lane = threadIdx.x & 31;

    int r = edge_idx(ei, warp);
    int c = edge_idx(ei, N_EDGES + warp);
    float norm = g_dinv[r] * g_dinv[c];

    float4 v = __ldg((const float4*)h + (size_t)r * 32 + lane);
    float* dst = g_agg + (size_t)c * IN_DIM + lane * 4;
    asm volatile("red.global.add.v4.f32 [%0], {%1, %2, %3, %4};"
                 :: "l"(dst),
                    "f"(v.x * norm), "f"(v.y * norm),
                    "f"(v.z * norm), "f"(v.w * norm)
                 : "memory");
}

// ---------------------------------------------------------------------------
// k4: fused MLP via packed f32x2 FFMA (even/odd-k partial sums):
//     out = relu(agg @ Wg + bg) @ Wf + bf
//     64 nodes/block, 256 threads; thread (tx,ty): 8 nodes x 4 cols (p1),
//     8 nodes x 2 cols (p2). Weights read K-contiguous from transposed globals.
// ---------------------------------------------------------------------------
__global__ void __launch_bounds__(256) k_mlp(const float* __restrict__ bg,
                                             const float* __restrict__ bf,
                                             float* __restrict__ out) {
    __shared__ float sA[64 * 128];   // 32 KB: input tile, then hidden tile

    int tid = threadIdx.x;
    int tx = tid & 31;       // 0..31
    int ty = tid >> 5;       // 0..7
    int node0 = blockIdx.x * 64;

    // load 64x128 input tile, row-major [node][k] (zero-pad past N)
    for (int i = tid; i < 64 * 32; i += 256) {
        int node = node0 + (i >> 5);
        float4 v = make_float4(0.f, 0.f, 0.f, 0.f);
        if (node < N_NODES) v = ((const float4*)g_agg)[(size_t)node * 32 + (i & 31)];
        ((float4*)sA)[i] = v;
    }
    __syncthreads();

    // ---- phase 1: hid = A @ Wg + bg  (cols 4tx..4tx+3, nodes 8ty..8ty+7) ----
    u64 acc[8][4];
    {
        float4 b = __ldg((const float4*)bg + tx);
        #pragma unroll
        for (int i = 0; i < 8; i++) {
            acc[i][0] = packf2(b.x, 0.f);
            acc[i][1] = packf2(b.y, 0.f);
            acc[i][2] = packf2(b.z, 0.f);
            acc[i][3] = packf2(b.w, 0.f);
        }
    }
    #pragma unroll 4
    for (int k = 0; k < 128; k += 2) {
        u64 w[4];
        #pragma unroll
        for (int j = 0; j < 4; j++)
            w[j] = *(const u64*)&g_Wgt[(4 * tx + j) * IN_DIM + k];   // LDG.64, L1-hot
        #pragma unroll
        for (int i = 0; i < 8; i++) {
            u64 a2 = *(const u64*)&sA[(8 * ty + i) * 128 + k];       // LDS.64 bcast
            #pragma unroll
            for (int j = 0; j < 4; j++)
                acc[i][j] = fma2(a2, w[j], acc[i][j]);
        }
    }
    __syncthreads();

    // horizontal add + relu -> hidden tile (row-major [node][c])
    #pragma unroll
    for (int i = 0; i < 8; i++) {
        float4 v;
        v.x = fmaxf(hadd2(acc[i][0]), 0.f);
        v.y = fmaxf(hadd2(acc[i][1]), 0.f);
        v.z = fmaxf(hadd2(acc[i][2]), 0.f);
        v.w = fmaxf(hadd2(acc[i][3]), 0.f);
        ((float4*)sA)[(8 * ty + i) * 32 + tx] = v;
    }
    __syncthreads();

    // ---- phase 2: out = hid @ Wf + bf  (cols 2tx..2tx+1) ----
    u64 o[8][2];
    {
        float2 b = __ldg((const float2*)bf + tx);
        #pragma unroll
        for (int i = 0; i < 8; i++) {
            o[i][0] = packf2(b.x, 0.f);
            o[i][1] = packf2(b.y, 0.f);
        }
    }
    #pragma unroll 4
    for (int k = 0; k < 128; k += 2) {
        u64 w0 = *(const u64*)&g_Wft[(2 * tx + 0) * HID + k];
        u64 w1 = *(const u64*)&g_Wft[(2 * tx + 1) * HID + k];
        #pragma unroll
        for (int i = 0; i < 8; i++) {
            u64 a2 = *(const u64*)&sA[(8 * ty + i) * 128 + k];
            o[i][0] = fma2(a2, w0, o[i][0]);
            o[i][1] = fma2(a2, w1, o[i][1]);
        }
    }

    #pragma unroll
    for (int i = 0; i < 8; i++) {
        int node = node0 + 8 * ty + i;
        if (node < N_NODES) {
            float2 v;
            v.x = hadd2(o[i][0]);
            v.y = hadd2(o[i][1]);
            ((float2*)out)[(size_t)node * 32 + tx] = v;
        }
    }
}

// ---------------------------------------------------------------------------
// launch — inputs: h[f32 N*128], edge_index[2*E int32-or-int64],
//          W_gcn[f32 128*128], b_gcn[f32 128], W_fc[f32 128*64], b_fc[f32 64]
// output: f32 N*64
// ---------------------------------------------------------------------------
extern "C" void kernel_launch(void* const* d_in, const int* in_sizes, int n_in,
                              void* d_out, int out_size) {
    const float* h  = (const float*)d_in[0];
    const void*  ei = d_in[1];
    const float* Wg = (const float*)d_in[2];
    const float* bg = (const float*)d_in[3];
    const float* Wf = (const float*)d_in[4];
    const float* bf = (const float*)d_in[5];
    float* out = (float*)d_out;

    k_init<<<(N_NODES + 255) / 256, 256>>>(ei, Wg, Wf);
    k_deg_count<<<(N_EDGES + 255) / 256, 256>>>(ei);
    k_dinv_self<<<(N_NODES * 32 + 255) / 256, 256>>>(h);
    k_scatter<<<(N_EDGES + 7) / 8, 256>>>(h, ei);       // one warp per edge
    k_mlp<<<(N_NODES + 63) / 64, 256>>>(bg, bf, out);
}

// round 4
// speedup vs baseline: 2.7624x; 2.7624x over previous
#include <cuda_runtime.h>
#include <cuda_bf16.h>
#include <cstdint>

#define N_NODES 50000
#define N_EDGES 800000
#define IN_DIM  128
#define HID     128
#define OUT_DIM 64

#define SCAN_BLOCKS ((N_NODES + 255) / 256)   // 196

// Scratch (device globals — no allocations allowed)
__device__ int   g_idx64;                       // 1 if edge_index is int64
__device__ int   g_cnt[N_NODES];                // raw in-degree (no self-loop)
__device__ int   g_off[N_NODES];                // CSR exclusive offsets
__device__ int   g_cur[N_NODES];                // fill cursors
__device__ int   g_bsum[256];                   // scan partials
__device__ float g_dinv[N_NODES];
__device__ float g_hs[(size_t)N_NODES * IN_DIM];// h[r] * dinv[r]
__device__ int   g_src[N_EDGES];                // CSR source node per slot

__device__ __forceinline__ int edge_idx(const void* ei, int i) {
    if (g_idx64) return (int)((const long long*)ei)[i];
    return ((const int*)ei)[i];
}

// ---------------------------------------------------------------------------
// k0: zero degree counters + dtype detection
// ---------------------------------------------------------------------------
__global__ void k_init(const void* __restrict__ ei) {
    int i = blockIdx.x * blockDim.x + threadIdx.x;
    if (i < N_NODES) g_cnt[i] = 0;
    if (blockIdx.x == 0) {
        __shared__ int s_ok;
        if (threadIdx.x == 0) s_ok = 1;
        __syncthreads();
        long long v = ((const long long*)ei)[threadIdx.x];  // 2KB, in-bounds either way
        if (v < 0 || v >= N_NODES) atomicAnd(&s_ok, 0);
        __syncthreads();
        if (threadIdx.x == 0) g_idx64 = s_ok;
    }
}

// k1: in-degree histogram over destination column
__global__ void k_count(const void* __restrict__ ei) {
    int e = blockIdx.x * blockDim.x + threadIdx.x;
    if (e < N_EDGES) atomicAdd(&g_cnt[edge_idx(ei, N_EDGES + e)], 1);
}

// ---------------------------------------------------------------------------
// CSR offset build: 3-kernel exclusive scan of g_cnt
// ---------------------------------------------------------------------------
__global__ void k_scanA() {
    __shared__ int s[256];
    int i = blockIdx.x * 256 + threadIdx.x;
    int v = (i < N_NODES) ? g_cnt[i] : 0;
    s[threadIdx.x] = v;
    __syncthreads();
    #pragma unroll
    for (int d = 1; d < 256; d <<= 1) {
        int t = (threadIdx.x >= d) ? s[threadIdx.x - d] : 0;
        __syncthreads();
        s[threadIdx.x] += t;
        __syncthreads();
    }
    if (i < N_NODES) g_off[i] = s[threadIdx.x] - v;   // exclusive within block
    if (threadIdx.x == 255) g_bsum[blockIdx.x] = s[255];
}

__global__ void k_scanB() {   // single block: exclusive scan of block sums
    __shared__ int s[256];
    int v = (threadIdx.x < SCAN_BLOCKS) ? g_bsum[threadIdx.x] : 0;
    s[threadIdx.x] = v;
    __syncthreads();
    #pragma unroll
    for (int d = 1; d < 256; d <<= 1) {
        int t = (threadIdx.x >= d) ? s[threadIdx.x - d] : 0;
        __syncthreads();
        s[threadIdx.x] += t;
        __syncthreads();
    }
    g_bsum[threadIdx.x] = s[threadIdx.x] - v;         // exclusive
}

__global__ void k_scanC() {   // finalize offsets, cursors, dinv
    int i = blockIdx.x * 256 + threadIdx.x;
    if (i < N_NODES) {
        int o = g_off[i] + g_bsum[blockIdx.x];
        g_off[i] = o;
        g_cur[i] = o;
        g_dinv[i] = rsqrtf((float)(g_cnt[i] + 1));    // +1 self-loop
    }
}

// k4: hs[r] = h[r] * dinv[r]   (one thread per float4)
__global__ void k_hs(const float* __restrict__ h) {
    int idx = blockIdx.x * blockDim.x + threadIdx.x;
    if (idx >= N_NODES * 32) return;
    float s = g_dinv[idx >> 5];
    float4 v = ((const float4*)h)[idx];
    v.x *= s; v.y *= s; v.z *= s; v.w *= s;
    ((float4*)g_hs)[idx] = v;
}

// k5: CSR fill (arbitrary order within a bucket — fp32 sum order differs
// from reference only in reassociation, well within 1e-3)
__global__ void k_fill(const void* __restrict__ ei) {
    int e = blockIdx.x * blockDim.x + threadIdx.x;
    if (e < N_EDGES) {
        int r = edge_idx(ei, e);
        int c = edge_idx(ei, N_EDGES + e);
        int p = atomicAdd(&g_cur[c], 1);
        g_src[p] = r;
    }
}

// ---------------------------------------------------------------------------
// k6: fused gather + MLP.
//   Block = 256 threads = 8 warps; 64 nodes per block.
//   Gather phase: warp wy processes nodes 8*wy..8*wy+7 sequentially;
//     lane holds one float4 of the 128-dim feature.
//     agg[n] = dinv[n] * (hs[n] + sum_{r in-edges} hs[r])  -> smem tile
//   MLP phase (proven R2 scalar code):
//     out = relu(tile @ Wg + bg) @ Wf + bf
// ---------------------------------------------------------------------------
__global__ void __launch_bounds__(256) k_gather_mlp(const float* __restrict__ Wg,
                                                    const float* __restrict__ bg,
                                                    const float* __restrict__ Wf,
                                                    const float* __restrict__ bf,
                                                    float* __restrict__ out) {
    __shared__ float sA[64 * 128];   // 32 KB: aggregated tile, then hidden tile

    int tid = threadIdx.x;
    int tx = tid & 31;       // lane
    int ty = tid >> 5;       // warp
    int node0 = blockIdx.x * 64;

    // ---- gather phase ----
    #pragma unroll
    for (int j = 0; j < 8; j++) {
        int node = node0 + ty * 8 + j;
        float4 acc = make_float4(0.f, 0.f, 0.f, 0.f);
        if (node < N_NODES) {
            acc = __ldg((const float4*)g_hs + (size_t)node * 32 + tx);  // self term
            int beg = g_off[node];
            int end = beg + g_cnt[node];
            for (int p = beg; p < end; p++) {
                int r = __ldg(g_src + p);                                // warp-uniform
                float4 v = __ldg((const float4*)g_hs + (size_t)r * 32 + tx);
                acc.x += v.x; acc.y += v.y; acc.z += v.z; acc.w += v.w;
            }
            float dn = g_dinv[node];
            acc.x *= dn; acc.y *= dn; acc.z *= dn; acc.w *= dn;
        }
        ((float4*)sA)[(ty * 8 + j) * 32 + tx] = acc;
    }
    __syncthreads();

    // ---- phase 1: hid = A @ Wg + bg ----
    float acc[8][4];
    {
        float4 b = __ldg((const float4*)bg + tx);
        #pragma unroll
        for (int i = 0; i < 8; i++) {
            acc[i][0] = b.x; acc[i][1] = b.y; acc[i][2] = b.z; acc[i][3] = b.w;
        }
    }
    #pragma unroll 4
    for (int k = 0; k < 128; k++) {
        float4 w = __ldg((const float4*)(Wg + k * 128) + tx);
        #pragma unroll
        for (int i = 0; i < 8; i++) {
            float a = sA[(8 * ty + i) * 128 + k];
            acc[i][0] += a * w.x;
            acc[i][1] += a * w.y;
            acc[i][2] += a * w.z;
            acc[i][3] += a * w.w;
        }
    }
    __syncthreads();

    // relu -> hidden tile
    #pragma unroll
    for (int i = 0; i < 8; i++) {
        float4 v;
        v.x = fmaxf(acc[i][0], 0.f);
        v.y = fmaxf(acc[i][1], 0.f);
        v.z = fmaxf(acc[i][2], 0.f);
        v.w = fmaxf(acc[i][3], 0.f);
        ((float4*)sA)[(8 * ty + i) * 32 + tx] = v;
    }
    __syncthreads();

    // ---- phase 2: out = hid @ Wf + bf ----
    float o[8][2];
    {
        float2 b = __ldg((const float2*)bf + tx);
        #pragma unroll
        for (int i = 0; i < 8; i++) { o[i][0] = b.x; o[i][1] = b.y; }
    }
    #pragma unroll 4
    for (int k = 0; k < 128; k++) {
        float2 w = __ldg((const float2*)(Wf + k * 64) + tx);
        #pragma unroll
        for (int i = 0; i < 8; i++) {
            float a = sA[(8 * ty + i) * 128 + k];
            o[i][0] += a * w.x;
            o[i][1] += a * w.y;
        }
    }

    #pragma unroll
    for (int i = 0; i < 8; i++) {
        int node = node0 + 8 * ty + i;
        if (node < N_NODES) {
            float2 v; v.x = o[i][0]; v.y = o[i][1];
            ((float2*)out)[(size_t)node * 32 + tx] = v;
        }
    }
}

// ---------------------------------------------------------------------------
// launch — inputs: h[f32 N*128], edge_index[2*E int32-or-int64],
//          W_gcn[f32 128*128], b_gcn[f32 128], W_fc[f32 128*64], b_fc[f32 64]
// output: f32 N*64
// ---------------------------------------------------------------------------
extern "C" void kernel_launch(void* const* d_in, const int* in_sizes, int n_in,
                              void* d_out, int out_size) {
    const float* h  = (const float*)d_in[0];
    const void*  ei = d_in[1];
    const float* Wg = (const float*)d_in[2];
    const float* bg = (const float*)d_in[3];
    const float* Wf = (const float*)d_in[4];
    const float* bf = (const float*)d_in[5];
    float* out = (float*)d_out;

    k_init <<<SCAN_BLOCKS, 256>>>(ei);
    k_count<<<(N_EDGES + 255) / 256, 256>>>(ei);
    k_scanA<<<SCAN_BLOCKS, 256>>>();
    k_scanB<<<1, 256>>>();
    k_scanC<<<SCAN_BLOCKS, 256>>>();
    k_hs   <<<(N_NODES * 32 + 255) / 256, 256>>>(h);
    k_fill <<<(N_EDGES + 255) / 256, 256>>>(ei);
    k_gather_mlp<<<(N_NODES + 63) / 64, 256>>>(Wg, bg, Wf, bf, out);
}